// round 5
// baseline (speedup 1.0000x reference)
#include <cuda_runtime.h>
#include <cuda_bf16.h>

// RocketConv: 84 ternary dilated depthwise kernels (alpha=-1, beta=2 at 3 taps).
// y_k[t] = -S(t) + 3*(s_a + s_b + s_c),  s_j = x[t + 4j - 16],  S = sum_j s_j
// Output layout (reference's double reshape) is flat (B, C, K, T):
//   out[((b*16 + c)*84 + k)*4096 + t]
//
// R3 change vs R2: float2 per thread (512 thr/block) instead of float4 (256).
// Taps drop 36->18 regs; __launch_bounds__(512,3) -> 1536 thr/SM (75% occ)
// to deepen the posted-store pipeline (R2: occ 40.6%, DRAM only 65%).

#define T_LEN    4096
#define SEG      1024
#define NTHREADS 512
#define HALO     16
#define TILE_F   (SEG + 2 * HALO)   // 1056 floats = 4.2 KB

__global__ __launch_bounds__(NTHREADS, 3)
void rocketconv_kernel(const float* __restrict__ x, float* __restrict__ out) {
    const int row = blockIdx.y;                 // b*16 + c
    const int seg = blockIdx.x * SEG;           // start t of this segment
    const float* __restrict__ xrow = x + (size_t)row * T_LEN;

    // Stage the row segment (+/-16 halo, zero padded) into shared memory.
    __shared__ __align__(16) float tile[TILE_F];
    for (int i = threadIdx.x; i < TILE_F; i += NTHREADS) {
        const int g = seg - HALO + i;
        tile[i] = (g >= 0 && g < T_LEN) ? xrow[g] : 0.0f;
    }
    __syncthreads();

    // Thread handles t0, t0+1 with t0 = seg + 2*tid.
    // Tap j for (t0+dt) is tile[2*tid + 4*j + dt] -> aligned float2 per tap.
    const float2* __restrict__ tp =
        reinterpret_cast<const float2*>(tile + 2 * threadIdx.x);   // tap j = tp[2*j]

    float2 t9[9];
    #pragma unroll
    for (int j = 0; j < 9; j++) t9[j] = tp[2 * j];

    float Sx = 0.f, Sy = 0.f;
    #pragma unroll
    for (int j = 0; j < 9; j++) { Sx += t9[j].x; Sy += t9[j].y; }
    const float nSx = -Sx, nSy = -Sy;

    // Output base for k=0 at this thread's t0; k-stride = 4096 floats = 2048 float2.
    float2* __restrict__ obase = reinterpret_cast<float2*>(
        out + (size_t)row * 84 * T_LEN + seg) + threadIdx.x;

    int k = 0;
    #pragma unroll
    for (int a = 0; a < 9; a++) {
        #pragma unroll
        for (int b = a + 1; b < 9; b++) {
            const float px = t9[a].x + t9[b].x;
            const float py = t9[a].y + t9[b].y;
            #pragma unroll
            for (int c = b + 1; c < 9; c++) {
                float2 r;
                r.x = fmaf(3.0f, px + t9[c].x, nSx);
                r.y = fmaf(3.0f, py + t9[c].y, nSy);
                // Streaming store: write-once 352 MB output, evict-first in L2.
                __stcs(obase + (size_t)k * (T_LEN / 2), r);
                k++;
            }
        }
    }
}

extern "C" void kernel_launch(void* const* d_in, const int* in_sizes, int n_in,
                              void* d_out, int out_size) {
    const float* x = (const float*)d_in[0];
    float* out = (float*)d_out;
    dim3 grid(T_LEN / SEG, 16 * 16);   // (4, 256)
    rocketconv_kernel<<<grid, NTHREADS>>>(x, out);
}

// round 8
// speedup vs baseline: 1.0048x; 1.0048x over previous
#include <cuda_runtime.h>
#include <cuda_bf16.h>

// RocketConv: 84 ternary dilated depthwise kernels (alpha=-1, beta=2 at 3 taps).
// y_k[t] = -S(t) + 3*(s_a + s_b + s_c),  s_j = x[t + 4j - 16],  S = sum_j s_j
// Output layout (reference's double reshape) is flat (B, C, K, T):
//   out[((b*16 + c)*84 + k)*4096 + t]
//
// R5 change vs R3: shrink block granularity for wave-quantization.
// R3 makespan decomposed as ~2 full waves of 23us blocks + ragged 136-block
// tail (matches 54us measured). SEG 1024->256, block 512->128 threads:
// 4096 blocks of 86KB output each, tail term ~= 1 block ~= 1.5us.

#define T_LEN    4096
#define SEG      256
#define NTHREADS 128
#define HALO     16
#define TILE_F   (SEG + 2 * HALO)   // 288 floats = 1.15 KB

__global__ __launch_bounds__(NTHREADS, 12)
void rocketconv_kernel(const float* __restrict__ x, float* __restrict__ out) {
    const int row = blockIdx.y;                 // b*16 + c
    const int seg = blockIdx.x * SEG;           // start t of this segment
    const float* __restrict__ xrow = x + (size_t)row * T_LEN;

    // Stage the row segment (+/-16 halo, zero padded) into shared memory.
    __shared__ __align__(16) float tile[TILE_F];
    for (int i = threadIdx.x; i < TILE_F; i += NTHREADS) {
        const int g = seg - HALO + i;
        tile[i] = (g >= 0 && g < T_LEN) ? xrow[g] : 0.0f;
    }
    __syncthreads();

    // Thread handles t0, t0+1 with t0 = seg + 2*tid.
    // Tap j for (t0+dt) is tile[2*tid + 4*j + dt] -> aligned float2 per tap.
    const float2* __restrict__ tp =
        reinterpret_cast<const float2*>(tile + 2 * threadIdx.x);   // tap j = tp[2*j]

    float2 t9[9];
    #pragma unroll
    for (int j = 0; j < 9; j++) t9[j] = tp[2 * j];

    float Sx = 0.f, Sy = 0.f;
    #pragma unroll
    for (int j = 0; j < 9; j++) { Sx += t9[j].x; Sy += t9[j].y; }
    const float nSx = -Sx, nSy = -Sy;

    // Output base for k=0 at this thread's t0; k-stride = 4096 floats = 2048 float2.
    float2* __restrict__ obase = reinterpret_cast<float2*>(
        out + (size_t)row * 84 * T_LEN + seg) + threadIdx.x;

    int k = 0;
    #pragma unroll
    for (int a = 0; a < 9; a++) {
        #pragma unroll
        for (int b = a + 1; b < 9; b++) {
            const float px = t9[a].x + t9[b].x;
            const float py = t9[a].y + t9[b].y;
            #pragma unroll
            for (int c = b + 1; c < 9; c++) {
                float2 r;
                r.x = fmaf(3.0f, px + t9[c].x, nSx);
                r.y = fmaf(3.0f, py + t9[c].y, nSy);
                // Streaming store: write-once 352 MB output, evict-first in L2.
                __stcs(obase + (size_t)k * (T_LEN / 2), r);
                k++;
            }
        }
    }
}

extern "C" void kernel_launch(void* const* d_in, const int* in_sizes, int n_in,
                              void* d_out, int out_size) {
    const float* x = (const float*)d_in[0];
    float* out = (float*)d_out;
    dim3 grid(T_LEN / SEG, 16 * 16);   // (16, 256)
    rocketconv_kernel<<<grid, NTHREADS>>>(x, out);
}